// round 16
// baseline (speedup 1.0000x reference)
#include <cuda_runtime.h>
#include <cuda_fp16.h>
#include <cstdint>
#include <cstddef>
#include <math.h>

#define DIMD 1024
#define HID  4096
#define NEXP 8
#define TOPK 3
#define NTOK 4096
#define MAXROWS (NTOK * TOPK + 512)

// ---------------- device scratch (allocations forbidden) --------------------
__device__ __half g_XH[(size_t)NTOK * DIMD];
__device__ __half g_W12H[(size_t)NEXP * DIMD * 2 * HID];
__device__ __half g_W3H[(size_t)NEXP * HID * DIMD];
__device__ __half g_HIDH[(size_t)MAXROWS * HID];
__device__ float g_OUTP[(size_t)MAXROWS * DIMD];
__device__ int   g_counts[NEXP];
__device__ int   g_offs[NEXP];
__device__ int   g_rows[NEXP * NTOK];
__device__ int   g_tok_e[NTOK * TOPK];
__device__ int   g_tok_pos[NTOK * TOPK];
__device__ float g_tok_w[NTOK * TOPK];
__device__ float g_aux;

// ---------------- helpers ---------------------------------------------------
__device__ __forceinline__ uint32_t smem_u32(const void* p) {
    uint32_t a;
    asm("{ .reg .u64 t; cvta.to.shared.u64 t, %1; cvt.u32.u64 %0, t; }" : "=r"(a) : "l"(p));
    return a;
}
__device__ __forceinline__ void cpa16(uint32_t s, const void* g) {
    asm volatile("cp.async.cg.shared.global [%0], [%1], 16;" :: "r"(s), "l"(g));
}
__device__ __forceinline__ void cp_commit() {
    asm volatile("cp.async.commit_group;" ::: "memory");
}
__device__ __forceinline__ void cp_wait2() {
    asm volatile("cp.async.wait_group 2;" ::: "memory");
}
__device__ __forceinline__ void ldsm4(uint32_t* r, uint32_t a) {
    asm volatile("ldmatrix.sync.aligned.m8n8.x4.shared.b16 {%0,%1,%2,%3}, [%4];"
                 : "=r"(r[0]), "=r"(r[1]), "=r"(r[2]), "=r"(r[3]) : "r"(a));
}
__device__ __forceinline__ void ldsm4t(uint32_t* r, uint32_t a) {
    asm volatile("ldmatrix.sync.aligned.m8n8.x4.trans.shared.b16 {%0,%1,%2,%3}, [%4];"
                 : "=r"(r[0]), "=r"(r[1]), "=r"(r[2]), "=r"(r[3]) : "r"(a));
}
__device__ __forceinline__ void mma16816(float* c, const uint32_t* a, const uint32_t* b) {
    asm volatile("mma.sync.aligned.m16n8k16.row.col.f32.f16.f16.f32 "
                 "{%0,%1,%2,%3}, {%4,%5,%6,%7}, {%8,%9}, {%0,%1,%2,%3};"
                 : "+f"(c[0]), "+f"(c[1]), "+f"(c[2]), "+f"(c[3])
                 : "r"(a[0]), "r"(a[1]), "r"(a[2]), "r"(a[3]), "r"(b[0]), "r"(b[1]));
}
__device__ __forceinline__ uint32_t pack2h(__half a, __half b) {
    return (uint32_t)__half_as_ushort(a) | ((uint32_t)__half_as_ushort(b) << 16);
}
__device__ __forceinline__ uint2 tohalf4(float4 v) {
    uint2 r;
    r.x = pack2h(__float2half_rn(v.x), __float2half_rn(v.y));
    r.y = pack2h(__float2half_rn(v.z), __float2half_rn(v.w));
    return r;
}

// ---------------- zero (must precede router atomics) -------------------------
__global__ void zero_kernel() {
    if (threadIdx.x < NEXP) g_counts[threadIdx.x] = 0;
    if (threadIdx.x == 0) g_aux = 0.f;
}

// ---------------- fused prep: x/w12 convert + router -------------------------
// b < 4096            : x fp32 -> fp16
// b < 69632           : w12 fp32 -> fp16
// b < 70144 (512 blks): router, 8 tokens per block (8 warps)
__global__ void prep_kernel(const float4* __restrict__ x, const float4* __restrict__ w12,
                            const float* __restrict__ rw, const float* __restrict__ rb) {
    const int b = blockIdx.x;
    if (b < 4096) {
        size_t i = (size_t)b * 256 + threadIdx.x;
        ((uint2*)g_XH)[i] = tohalf4(x[i]);
        return;
    }
    if (b < 69632) {
        size_t i = (size_t)(b - 4096) * 256 + threadIdx.x;
        ((uint2*)g_W12H)[i] = tohalf4(w12[i]);
        return;
    }
    // ---- router ----
    __shared__ float4 s_rw[NEXP * DIMD / 4];   // 32 KB
    for (int i = threadIdx.x; i < NEXP * DIMD / 4; i += 256) s_rw[i] = ((const float4*)rw)[i];
    __syncthreads();
    const int warp = threadIdx.x >> 5, lane = threadIdx.x & 31;
    const int t = (b - 69632) * 8 + warp;
    const float4* xr = x + (size_t)t * (DIMD / 4);
    float acc[NEXP];
#pragma unroll
    for (int e = 0; e < NEXP; ++e) acc[e] = 0.f;
#pragma unroll
    for (int i = 0; i < 8; ++i) {
        float4 xv = xr[lane + i * 32];
#pragma unroll
        for (int e = 0; e < NEXP; ++e) {
            float4 wv = s_rw[e * 256 + lane + i * 32];
            acc[e] += xv.x * wv.x + xv.y * wv.y + xv.z * wv.z + xv.w * wv.w;
        }
    }
#pragma unroll
    for (int e = 0; e < NEXP; ++e)
#pragma unroll
        for (int off = 16; off > 0; off >>= 1) acc[e] += __shfl_xor_sync(0xFFFFFFFFu, acc[e], off);
    if (lane == 0) {
        float s[NEXP], aux = 0.f;
#pragma unroll
        for (int e = 0; e < NEXP; ++e) {
            float lg = acc[e] + rb[e];
            aux += lg * lg;
            s[e] = 1.f / (1.f + expf(-lg));
        }
        atomicAdd(&g_aux, aux);
        int idx[TOPK]; float sc[TOPK]; bool used[NEXP];
#pragma unroll
        for (int e = 0; e < NEXP; ++e) used[e] = false;
#pragma unroll
        for (int k = 0; k < TOPK; ++k) {
            int best = 0; float bv = -1e30f;
#pragma unroll
            for (int e = 0; e < NEXP; ++e)
                if (!used[e] && s[e] > bv) { bv = s[e]; best = e; }
            used[best] = true; idx[k] = best; sc[k] = bv;
        }
        float tot = sc[0] + sc[1] + sc[2] + 1e-6f;
#pragma unroll
        for (int k = 0; k < TOPK; ++k) {
            int e = idx[k];
            int pos = atomicAdd(&g_counts[e], 1);
            g_rows[e * NTOK + pos] = t;
            g_tok_e[t * TOPK + k] = e;
            g_tok_pos[t * TOPK + k] = pos;
            g_tok_w[t * TOPK + k] = sc[k] / tot;
        }
    }
}

__global__ void prefix_kernel() {
    int s = 0;
    for (int e = 0; e < NEXP; ++e) { g_offs[e] = s; s += g_counts[e]; }
}

// ---------------- GEMM1 (+ fused w3 converter CTAs) --------------------------
// y < 64 : GEMM1 CTA: 128 rows x (64 W1-cols + 64 W2-cols), R13 config.
// y >= 64: w3 fp32 -> fp16 converter (8 CTAs per expert, grid-stride).
#define G1_STG 18432
#define G1_DYN (4 * G1_STG + 512)
#define NCH1 32

__global__ __launch_bounds__(256, 2) void gemm1_kernel(const float4* __restrict__ w3raw) {
    const int e = blockIdx.z;
    if (blockIdx.y >= 64) {
        // ---- w3 converter: slice (blockIdx.y - 64) of expert e ----
        const int s = blockIdx.y - 64;
        const size_t base = (size_t)e * (HID * DIMD / 4) + (size_t)s * (HID * DIMD / 32);
        const int n = HID * DIMD / 32;  // 131072 float4 per slice
#pragma unroll 4
        for (int j = threadIdx.x; j < n; j += 256) {
            size_t i = base + j;
            ((uint2*)g_W3H)[i] = tohalf4(w3raw[i]);
        }
        return;
    }

    extern __shared__ __align__(128) char smem[];
    const int ne = g_counts[e];
    const int mtile = blockIdx.x;
    if (mtile * 128 >= ne) return;
    const int ntile = blockIdx.y;
    const int tid = threadIdx.x, wid = tid >> 5, lane = tid & 31;

    int* rows_s = (int*)(smem + 4 * G1_STG);
    const uint32_t sbase = smem_u32(smem);
    for (int r = tid; r < 128; r += 256) {
        int lr = mtile * 128 + r;
        rows_s[r] = (lr < ne) ? g_rows[e * NTOK + lr] : 0;
    }
    __syncthreads();

    const size_t wb = (size_t)e * DIMD * 2 * HID;

    auto issue = [&](int c) {
        const int k0 = c * 32;
        const uint32_t bufA = sbase + (c & 3) * G1_STG;
        const uint32_t bufB = bufA + 10240;
#pragma unroll
        for (int j = 0; j < 2; ++j) {  // A: 128 rows x 64 B (stride 80)
            int i = tid + j * 256;
            int row = i >> 2, c4 = i & 3;
            size_t off = (size_t)rows_s[row] * DIMD + k0;
            cpa16(bufA + row * 80 + c4 * 16, (const char*)(g_XH + off) + c4 * 16);
        }
#pragma unroll
        for (int j = 0; j < 2; ++j) {  // B: 32 k-rows x 256 B (W1|W2 packed)
            int i = tid + j * 256;
            int r = (i >> 4) & 31, cc = i & 15;
            int half = cc >> 3;  // 0 = W1, 1 = W2
            const char* g = (const char*)(g_W12H + wb + (size_t)(k0 + r) * (2 * HID) +
                                          half * HID + ntile * 64 + (cc & 7) * 8);
            cpa16(bufB + r * 256 + ((cc ^ (r & 7)) << 4), g);
        }
    };

    const int mw = wid >> 2, nw = wid & 3;   // 2 x 4 warp grid
    const int m0 = mw * 64, n0 = nw * 16;
    float acc1[4][2][4], acc2[4][2][4];
#pragma unroll
    for (int a = 0; a < 4; ++a)
#pragma unroll
        for (int b = 0; b < 2; ++b)
#pragma unroll
            for (int r = 0; r < 4; ++r) { acc1[a][b][r] = 0.f; acc2[a][b][r] = 0.f; }

    auto compute = [&](int c) {
        const uint32_t bufA = sbase + (c & 3) * G1_STG;
        const uint32_t bufB = bufA + 10240;
#pragma unroll
        for (int ks = 0; ks < 32; ks += 16) {
            uint32_t ah[4][4];
#pragma unroll
            for (int mi = 0; mi < 4; ++mi)
                ldsm4(ah[mi], bufA + (m0 + mi * 16 + (lane & 15)) * 80 + ks * 2 + (lane >> 4) * 16);
            uint32_t b1[4], b2[4];
            const int grp = lane >> 3;
            const int kr = ks + ((grp & 1) << 3) + (lane & 7);
            {
                int cc = (n0 >> 3) + (grp >> 1);          // W1 half: chunks 0..7
                ldsm4t(b1, bufB + kr * 256 + ((cc ^ (kr & 7)) << 4));
                cc += 8;                                   // W2 half: chunks 8..15
                ldsm4t(b2, bufB + kr * 256 + ((cc ^ (kr & 7)) << 4));
            }
#pragma unroll
            for (int mi = 0; mi < 4; ++mi)
#pragma unroll
                for (int nj = 0; nj < 2; ++nj) {
                    mma16816(acc1[mi][nj], ah[mi], &b1[nj * 2]);
                    mma16816(acc2[mi][nj], ah[mi], &b2[nj * 2]);
                }
        }
    };

    issue(0); cp_commit();
    issue(1); cp_commit();

    for (int c = 0; c < NCH1; ++c) {
        if (c + 2 < NCH1) issue(c + 2);
        cp_commit();
        cp_wait2();
        __syncthreads();
        compute(c);
    }

    // epilogue: h = silu(a1) * a2 -> fp16
    const int rowbase = g_offs[e];
#pragma unroll
    for (int mi = 0; mi < 4; ++mi)
#pragma unroll
        for (int h = 0; h < 2; ++h) {
            int rl = m0 + mi * 16 + h * 8 + (lane >> 2);
            int lr = mtile * 128 + rl;
            if (lr < ne) {
                size_t rowb = (size_t)(rowbase + lr) * HID + ntile * 64;
#pragma unroll
                for (int nj = 0; nj < 2; ++nj) {
                    float a1a = acc1[mi][nj][h * 2], a1b = acc1[mi][nj][h * 2 + 1];
                    float a2a = acc2[mi][nj][h * 2], a2b = acc2[mi][nj][h * 2 + 1];
                    float ha = a1a / (1.f + expf(-a1a)) * a2a;
                    float hb = a1b / (1.f + expf(-a1b)) * a2b;
                    int col = n0 + nj * 8 + 2 * (lane & 3);
                    *(uint32_t*)&g_HIDH[rowb + col] =
                        pack2h(__float2half_rn(ha), __float2half_rn(hb));
                }
            }
        }
}

// ---------------- GEMM2: out_part = hidden @ W3 (proven R10/R13 version) ----
#define G2_STG 18432
#define G2_DYN (4 * G2_STG)
#define NCH2 128

__global__ __launch_bounds__(256, 2) void gemm2_kernel() {
    extern __shared__ __align__(128) char smem[];
    const int e = blockIdx.z;
    const int ne = g_counts[e];
    const int mtile = blockIdx.x;
    if (mtile * 128 >= ne) return;
    const int ntile = blockIdx.y;
    const int tid = threadIdx.x, wid = tid >> 5, lane = tid & 31;

    const uint32_t sbase = smem_u32(smem);
    const int row0 = g_offs[e] + mtile * 128;
    const size_t wb = (size_t)e * HID * DIMD;

    auto issue = [&](int c) {
        const int k0 = c * 32;
        const uint32_t bufA = sbase + (c & 3) * G2_STG;
        const uint32_t bufB = bufA + 10240;
#pragma unroll
        for (int j = 0; j < 2; ++j) {  // A: 128 rows x 64 B
            int i = tid + j * 256;
            int row = i >> 2, c4 = i & 3;
            size_t off = (size_t)(row0 + row) * HID + k0;
            cpa16(bufA + row * 80 + c4 * 16, (const char*)(g_HIDH + off) + c4 * 16);
        }
#pragma unroll
        for (int j = 0; j < 2; ++j) {  // B: 32 k-rows x 256 B
            int i = tid + j * 256;
            int r = (i >> 4) & 31, cc = i & 15;
            const char* g = (const char*)(g_W3H + wb + (size_t)(k0 + r) * DIMD +
                                          ntile * 128 + cc * 8);
            cpa16(bufB + r * 256 + ((cc ^ (r & 7)) << 4), g);
        }
    };

    const int mw = wid >> 2, nw = wid & 3;
    const int m0 = mw * 64, n0 = nw * 32;
    float acc[4][4][4];
#pragma unroll
    for (int a = 0; a < 4; ++a)
#pragma unroll
        for (int b = 0; b < 4; ++b)
#pragma unroll
            for (int r = 0; r < 4; ++r) acc[a][b][r] = 0.f;

    issue(0); cp_commit();
    issue(1); cp_commit();

    for (int c = 0; c < NCH2; ++c) {
        if (c + 2 < NCH2) issue(c + 2);
        cp_commit();
        cp_wait2();
        __syncthreads();
        const uint32_t bufA = sbase + (c & 3) * G2_STG;
        const uint32_t bufB = bufA + 10240;
#pragma unroll
        for (int ks = 0; ks < 32; ks += 16) {
            uint32_t ah[4][4];
#pragma unroll
            for (int mi = 0; mi < 4; ++mi)
                ldsm4(ah[mi], bufA + (m0 + mi * 16 + (lane & 15)) * 80 + ks * 2 + (lane >> 4) * 16);
            uint32_t bh[2][4];
            const int grp = lane >> 3;
            const int kr = ks + ((grp & 1) << 3) + (lane & 7);
#pragma unroll
            for (int gj = 0; gj < 2; ++gj) {
                int cc = ((n0 + (gj << 4)) >> 3) + (grp >> 1);
                ldsm4t(bh[gj], bufB + kr * 256 + ((cc ^ (kr & 7)) << 4));
            }
#pragma unroll
            for (int mi = 0; mi < 4; ++mi)
#pragma unroll
                for (int nj = 0; nj < 4; ++nj)
                    mma16816(acc[mi][nj], ah[mi], &bh[nj >> 1][(nj & 1) * 2]);
        }
    }

#pragma unroll
    for (int mi = 0; mi < 4; ++mi)
#pragma unroll
        for (int h = 0; h < 2; ++h) {
            int rl = m0 + mi * 16 + h * 8 + (lane >> 2);
            int lr = mtile * 128 + rl;
            if (lr < ne) {
                size_t rowb = (size_t)(row0 + rl) * DIMD + ntile * 128;
#pragma unroll
                for (int nj = 0; nj < 4; ++nj) {
                    int col = n0 + nj * 8 + 2 * (lane & 3);
                    float2 v = make_float2(acc[mi][nj][h * 2], acc[mi][nj][h * 2 + 1]);
                    *(float2*)&g_OUTP[rowb + col] = v;
                }
            }
        }
}

// ---------------- combine ---------------------------------------------------
__global__ void combine_kernel(float* __restrict__ out, int out_size) {
    const int t = blockIdx.x, tid = threadIdx.x;
    float4 acc = make_float4(0.f, 0.f, 0.f, 0.f);
#pragma unroll
    for (int k = 0; k < TOPK; ++k) {
        int e = g_tok_e[t * TOPK + k];
        int row = g_offs[e] + g_tok_pos[t * TOPK + k];
        float w = g_tok_w[t * TOPK + k];
        float4 v = ((const float4*)(g_OUTP + (size_t)row * DIMD))[tid];
        acc.x += w * v.x; acc.y += w * v.y; acc.z += w * v.z; acc.w += w * v.w;
    }
    ((float4*)(out + (size_t)t * DIMD))[tid] = acc;
    if (t == 0 && tid == 0 && out_size > NTOK * DIMD)
        out[NTOK * DIMD] = 0.01f * g_aux / (float)(NTOK * NEXP);
}

// ---------------- launch -----------------------------------------------------
extern "C" void kernel_launch(void* const* d_in, const int* in_sizes, int n_in,
                              void* d_out, int out_size) {
    const float *x = 0, *rw = 0, *rb = 0, *w12 = 0, *w3 = 0;
    for (int i = 0; i < n_in; ++i) {
        switch (in_sizes[i]) {
            case 4194304:  x   = (const float*)d_in[i]; break;
            case 8192:     rw  = (const float*)d_in[i]; break;
            case 8:        rb  = (const float*)d_in[i]; break;
            case 67108864: w12 = (const float*)d_in[i]; break;
            case 33554432: w3  = (const float*)d_in[i]; break;
        }
    }
    if (!x || !rw || !rb || !w12 || !w3) {
        x = (const float*)d_in[0]; rw = (const float*)d_in[1]; rb = (const float*)d_in[2];
        w12 = (const float*)d_in[3]; w3 = (const float*)d_in[4];
    }
    float* out = (float*)d_out;

    cudaFuncSetAttribute(gemm1_kernel, cudaFuncAttributeMaxDynamicSharedMemorySize, G1_DYN);
    cudaFuncSetAttribute(gemm2_kernel, cudaFuncAttributeMaxDynamicSharedMemorySize, G2_DYN);

    zero_kernel<<<1, 32>>>();
    prep_kernel<<<70144, 256>>>((const float4*)x, (const float4*)w12, rw, rb);
    prefix_kernel<<<1, 1>>>();
    gemm1_kernel<<<dim3(32, 72, NEXP), 256, G1_DYN>>>((const float4*)w3);
    gemm2_kernel<<<dim3(32, 8, NEXP), 256, G2_DYN>>>();
    combine_kernel<<<NTOK, 256>>>(out, out_size);
}

// round 17
// speedup vs baseline: 1.5937x; 1.5937x over previous
#include <cuda_runtime.h>
#include <cuda_fp16.h>
#include <cstdint>
#include <cstddef>
#include <math.h>

#define DIMD 1024
#define HID  4096
#define NEXP 8
#define TOPK 3
#define NTOK 4096
#define MAXROWS (NTOK * TOPK + 512)

// ---------------- device scratch (allocations forbidden) --------------------
__device__ __half g_XH[(size_t)NTOK * DIMD];
__device__ __half g_W12H[(size_t)NEXP * DIMD * 2 * HID];
__device__ __half g_W3H[(size_t)NEXP * HID * DIMD];
__device__ __half g_HIDH[(size_t)MAXROWS * HID];
__device__ float g_OUTP[(size_t)MAXROWS * DIMD];
__device__ int   g_counts[NEXP];
__device__ int   g_offs[NEXP];
__device__ int   g_rows[NEXP * NTOK];
__device__ int   g_tok_e[NTOK * TOPK];
__device__ int   g_tok_pos[NTOK * TOPK];
__device__ float g_tok_w[NTOK * TOPK];
__device__ float g_aux;

// ---------------- helpers ---------------------------------------------------
__device__ __forceinline__ uint32_t smem_u32(const void* p) {
    uint32_t a;
    asm("{ .reg .u64 t; cvta.to.shared.u64 t, %1; cvt.u32.u64 %0, t; }" : "=r"(a) : "l"(p));
    return a;
}
__device__ __forceinline__ void cpa16(uint32_t s, const void* g) {
    asm volatile("cp.async.cg.shared.global [%0], [%1], 16;" :: "r"(s), "l"(g));
}
__device__ __forceinline__ void cp_commit() {
    asm volatile("cp.async.commit_group;" ::: "memory");
}
__device__ __forceinline__ void cp_wait2() {
    asm volatile("cp.async.wait_group 2;" ::: "memory");
}
__device__ __forceinline__ void ldsm4(uint32_t* r, uint32_t a) {
    asm volatile("ldmatrix.sync.aligned.m8n8.x4.shared.b16 {%0,%1,%2,%3}, [%4];"
                 : "=r"(r[0]), "=r"(r[1]), "=r"(r[2]), "=r"(r[3]) : "r"(a));
}
__device__ __forceinline__ void ldsm4t(uint32_t* r, uint32_t a) {
    asm volatile("ldmatrix.sync.aligned.m8n8.x4.trans.shared.b16 {%0,%1,%2,%3}, [%4];"
                 : "=r"(r[0]), "=r"(r[1]), "=r"(r[2]), "=r"(r[3]) : "r"(a));
}
__device__ __forceinline__ void mma16816(float* c, const uint32_t* a, const uint32_t* b) {
    asm volatile("mma.sync.aligned.m16n8k16.row.col.f32.f16.f16.f32 "
                 "{%0,%1,%2,%3}, {%4,%5,%6,%7}, {%8,%9}, {%0,%1,%2,%3};"
                 : "+f"(c[0]), "+f"(c[1]), "+f"(c[2]), "+f"(c[3])
                 : "r"(a[0]), "r"(a[1]), "r"(a[2]), "r"(a[3]), "r"(b[0]), "r"(b[1]));
}
__device__ __forceinline__ uint32_t pack2h(__half a, __half b) {
    return (uint32_t)__half_as_ushort(a) | ((uint32_t)__half_as_ushort(b) << 16);
}
__device__ __forceinline__ uint2 tohalf4(float4 v) {
    uint2 r;
    r.x = pack2h(__float2half_rn(v.x), __float2half_rn(v.y));
    r.y = pack2h(__float2half_rn(v.z), __float2half_rn(v.w));
    return r;
}

// ---------------- fused prep: zero + x/w12/w3 convert ------------------------
// Each block covers 512 float4; each thread converts 2 (MLP-2, coalesced).
// Blocks: [0,2048) x, [2048,34816) w12, [34816,51200) w3, 51200 = zero.
__global__ void prep_kernel(const float4* __restrict__ x, const float4* __restrict__ w12,
                            const float4* __restrict__ w3) {
    const int b = blockIdx.x;
    if (b >= 51200) {
        if (threadIdx.x < NEXP) g_counts[threadIdx.x] = 0;
        if (threadIdx.x == 0) g_aux = 0.f;
        return;
    }
    const float4* src;
    __half* dst;
    size_t base;
    if (b < 2048) {
        src = x;  dst = g_XH;   base = (size_t)b * 512;
    } else if (b < 34816) {
        src = w12; dst = g_W12H; base = (size_t)(b - 2048) * 512;
    } else {
        src = w3;  dst = g_W3H;  base = (size_t)(b - 34816) * 512;
    }
    size_t i0 = base + threadIdx.x;
    size_t i1 = i0 + 256;
    float4 v0 = src[i0];
    float4 v1 = src[i1];
    ((uint2*)dst)[i0] = tohalf4(v0);
    ((uint2*)dst)[i1] = tohalf4(v1);
}

__global__ void router_kernel(const float* __restrict__ x, const float* __restrict__ rw,
                              const float* __restrict__ rb) {
    __shared__ float4 s_rw[NEXP * DIMD / 4];
    for (int i = threadIdx.x; i < NEXP * DIMD / 4; i += 128) s_rw[i] = ((const float4*)rw)[i];
    __syncthreads();
    const int warp = threadIdx.x >> 5, lane = threadIdx.x & 31;
    const int t = blockIdx.x * 4 + warp;
    const float4* xr = (const float4*)(x + (size_t)t * DIMD);
    float acc[NEXP];
#pragma unroll
    for (int e = 0; e < NEXP; ++e) acc[e] = 0.f;
#pragma unroll
    for (int i = 0; i < 8; ++i) {
        float4 xv = xr[lane + i * 32];
#pragma unroll
        for (int e = 0; e < NEXP; ++e) {
            float4 wv = s_rw[e * 256 + lane + i * 32];
            acc[e] += xv.x * wv.x + xv.y * wv.y + xv.z * wv.z + xv.w * wv.w;
        }
    }
#pragma unroll
    for (int e = 0; e < NEXP; ++e)
#pragma unroll
        for (int off = 16; off > 0; off >>= 1) acc[e] += __shfl_xor_sync(0xFFFFFFFFu, acc[e], off);
    if (lane == 0) {
        float s[NEXP], aux = 0.f;
#pragma unroll
        for (int e = 0; e < NEXP; ++e) {
            float lg = acc[e] + rb[e];
            aux += lg * lg;
            s[e] = 1.f / (1.f + expf(-lg));
        }
        atomicAdd(&g_aux, aux);
        int idx[TOPK]; float sc[TOPK]; bool used[NEXP];
#pragma unroll
        for (int e = 0; e < NEXP; ++e) used[e] = false;
#pragma unroll
        for (int k = 0; k < TOPK; ++k) {
            int best = 0; float bv = -1e30f;
#pragma unroll
            for (int e = 0; e < NEXP; ++e)
                if (!used[e] && s[e] > bv) { bv = s[e]; best = e; }
            used[best] = true; idx[k] = best; sc[k] = bv;
        }
        float tot = sc[0] + sc[1] + sc[2] + 1e-6f;
#pragma unroll
        for (int k = 0; k < TOPK; ++k) {
            int e = idx[k];
            int pos = atomicAdd(&g_counts[e], 1);
            g_rows[e * NTOK + pos] = t;
            g_tok_e[t * TOPK + k] = e;
            g_tok_pos[t * TOPK + k] = pos;
            g_tok_w[t * TOPK + k] = sc[k] / tot;
        }
    }
}

__global__ void prefix_kernel() {
    int s = 0;
    for (int e = 0; e < NEXP; ++e) { g_offs[e] = s; s += g_counts[e]; }
}

// ---------------- GEMM1: hidden = silu(x@W1) * (x@W2)  (R10 config) ---------
// CTA: 64 rows x (128 W1-cols + 128 W2-cols). Stage = 5120 + 2*8192 = 21504;
// 4 stages; occ 2.
#define G1_STG 21504
#define G1_DYN (4 * G1_STG + 512)
#define NCH1 32

__global__ __launch_bounds__(256, 2) void gemm1_kernel() {
    extern __shared__ __align__(128) char smem[];
    const int e = blockIdx.z;
    const int ne = g_counts[e];
    const int mtile = blockIdx.x;
    if (mtile * 64 >= ne) return;
    const int ntile = blockIdx.y;
    const int tid = threadIdx.x, wid = tid >> 5, lane = tid & 31;

    int* rows_s = (int*)(smem + 4 * G1_STG);
    const uint32_t sbase = smem_u32(smem);
    if (tid < 64) {
        int lr = mtile * 64 + tid;
        rows_s[tid] = (lr < ne) ? g_rows[e * NTOK + lr] : 0;
    }
    __syncthreads();

    const size_t wb = (size_t)e * DIMD * 2 * HID;

    auto issue = [&](int c) {
        const int k0 = c * 32;
        const uint32_t bufA = sbase + (c & 3) * G1_STG;
        const uint32_t bufB = bufA + 5120;
        {   // A: 64 rows x 64 B
            int row = tid >> 2, c4 = tid & 3;
            size_t off = (size_t)rows_s[row] * DIMD + k0;
            cpa16(bufA + row * 80 + c4 * 16, (const char*)(g_XH + off) + c4 * 16);
        }
#pragma unroll
        for (int j = 0; j < 4; ++j) {  // B: mats {W1,W2} x 32 k-rows x 256B
            int i = tid + j * 256;
            int mat = i >> 9, r = (i >> 4) & 31, cc = i & 15;
            const char* g = (const char*)(g_W12H + wb + (size_t)(k0 + r) * (2 * HID) +
                                          mat * HID + ntile * 128 + cc * 8);
            cpa16(bufB + mat * 8192 + r * 256 + ((cc ^ (r & 7)) << 4), g);
        }
    };

    const int mw = wid >> 2, nw = wid & 3;
    const int m0 = mw * 32, n0 = nw * 32;
    float acc1[2][4][4], acc2[2][4][4];
#pragma unroll
    for (int a = 0; a < 2; ++a)
#pragma unroll
        for (int b = 0; b < 4; ++b)
#pragma unroll
            for (int r = 0; r < 4; ++r) { acc1[a][b][r] = 0.f; acc2[a][b][r] = 0.f; }

    issue(0); cp_commit();
    issue(1); cp_commit();

    for (int c = 0; c < NCH1; ++c) {
        if (c + 2 < NCH1) issue(c + 2);
        cp_commit();
        cp_wait2();
        __syncthreads();
        const uint32_t bufA = sbase + (c & 3) * G1_STG;
        const uint32_t bufB = bufA + 5120;
#pragma unroll
        for (int ks = 0; ks < 32; ks += 16) {
            uint32_t ah[2][4];
#pragma unroll
            for (int mi = 0; mi < 2; ++mi)
                ldsm4(ah[mi], bufA + (m0 + mi * 16 + (lane & 15)) * 80 + ks * 2 + (lane >> 4) * 16);
            uint32_t b1[2][4], b2[2][4];
            const int grp = lane >> 3;
            const int kr = ks + ((grp & 1) << 3) + (lane & 7);
#pragma unroll
            for (int gj = 0; gj < 2; ++gj) {
                int cc = ((n0 + (gj << 4)) >> 3) + (grp >> 1);
                uint32_t off = kr * 256 + ((cc ^ (kr & 7)) << 4);
                ldsm4t(b1[gj], bufB + off);
                ldsm4t(b2[gj], bufB + 8192 + off);
            }
#pragma unroll
            for (int mi = 0; mi < 2; ++mi)
#pragma unroll
                for (int nj = 0; nj < 4; ++nj) {
                    mma16816(acc1[mi][nj], ah[mi], &b1[nj >> 1][(nj & 1) * 2]);
                    mma16816(acc2[mi][nj], ah[mi], &b2[nj >> 1][(nj & 1) * 2]);
                }
        }
    }

    // epilogue: h = silu(a1) * a2 -> fp16
    const int rowbase = g_offs[e];
#pragma unroll
    for (int mi = 0; mi < 2; ++mi)
#pragma unroll
        for (int h = 0; h < 2; ++h) {
            int rl = m0 + mi * 16 + h * 8 + (lane >> 2);
            int lr = mtile * 64 + rl;
            if (lr < ne) {
                size_t rowb = (size_t)(rowbase + lr) * HID + ntile * 128;
#pragma unroll
                for (int nj = 0; nj < 4; ++nj) {
                    float a1a = acc1[mi][nj][h * 2], a1b = acc1[mi][nj][h * 2 + 1];
                    float a2a = acc2[mi][nj][h * 2], a2b = acc2[mi][nj][h * 2 + 1];
                    float ha = a1a / (1.f + expf(-a1a)) * a2a;
                    float hb = a1b / (1.f + expf(-a1b)) * a2b;
                    int col = n0 + nj * 8 + 2 * (lane & 3);
                    *(uint32_t*)&g_HIDH[rowb + col] =
                        pack2h(__float2half_rn(ha), __float2half_rn(hb));
                }
            }
        }
}

// ---------------- GEMM2: out_part = hidden @ W3 (R10 config) ----------------
#define G2_STG 18432
#define G2_DYN (4 * G2_STG)
#define NCH2 128

__global__ __launch_bounds__(256, 2) void gemm2_kernel() {
    extern __shared__ __align__(128) char smem[];
    const int e = blockIdx.z;
    const int ne = g_counts[e];
    const int mtile = blockIdx.x;
    if (mtile * 128 >= ne) return;
    const int ntile = blockIdx.y;
    const int tid = threadIdx.x, wid = tid >> 5, lane = tid & 31;

    const uint32_t sbase = smem_u32(smem);
    const int row0 = g_offs[e] + mtile * 128;
    const size_t wb = (size_t)e * HID * DIMD;

    auto issue = [&](int c) {
        const int k0 = c * 32;
        const uint32_t bufA = sbase + (c & 3) * G2_STG;
        const uint32_t bufB = bufA + 10240;
#pragma unroll
        for (int j = 0; j < 2; ++j) {  // A: 128 rows x 64 B
            int i = tid + j * 256;
            int row = i >> 2, c4 = i & 3;
            size_t off = (size_t)(row0 + row) * HID + k0;
            cpa16(bufA + row * 80 + c4 * 16, (const char*)(g_HIDH + off) + c4 * 16);
        }
#pragma unroll
        for (int j = 0; j < 2; ++j) {  // B: 32 k-rows x 256 B
            int i = tid + j * 256;
            int r = (i >> 4) & 31, cc = i & 15;
            const char* g = (const char*)(g_W3H + wb + (size_t)(k0 + r) * DIMD +
                                          ntile * 128 + cc * 8);
            cpa16(bufB + r * 256 + ((cc ^ (r & 7)) << 4), g);
        }
    };

    const int mw = wid >> 2, nw = wid & 3;
    const int m0 = mw * 64, n0 = nw * 32;
    float acc[4][4][4];
#pragma unroll
    for (int a = 0; a < 4; ++a)
#pragma unroll
        for (int b = 0; b < 4; ++b)
#pragma unroll
            for (int r = 0; r < 4; ++r) acc[a][b][r] = 0.f;

    issue(0); cp_commit();
    issue(1); cp_commit();

    for (int c = 0; c < NCH2; ++c) {
        if (c + 2 < NCH2) issue(c + 2);
        cp_commit();
        cp_wait2();
        __syncthreads();
        const uint32_t bufA = sbase + (c & 3) * G2_STG;
        const uint32_t bufB = bufA + 10240;
#pragma unroll
        for (int ks = 0; ks < 32; ks += 16) {
            uint32_t ah[4][4];
#pragma unroll
            for (int mi = 0; mi < 4; ++mi)
                ldsm4(ah[mi], bufA + (m0 + mi * 16 + (lane & 15)) * 80 + ks * 2 + (lane >> 4) * 16);
            uint32_t bh[2][4];
            const int grp = lane >> 3;
            const int kr = ks + ((grp & 1) << 3) + (lane & 7);
#pragma unroll
            for (int gj = 0; gj < 2; ++gj) {
                int cc = ((n0 + (gj << 4)) >> 3) + (grp >> 1);
                ldsm4t(bh[gj], bufB + kr * 256 + ((cc ^ (kr & 7)) << 4));
            }
#pragma unroll
            for (int mi = 0; mi < 4; ++mi)
#pragma unroll
                for (int nj = 0; nj < 4; ++nj)
                    mma16816(acc[mi][nj], ah[mi], &bh[nj >> 1][(nj & 1) * 2]);
        }
    }

#pragma unroll
    for (int mi = 0; mi < 4; ++mi)
#pragma unroll
        for (int h = 0; h < 2; ++h) {
            int rl = m0 + mi * 16 + h * 8 + (lane >> 2);
            int lr = mtile * 128 + rl;
            if (lr < ne) {
                size_t rowb = (size_t)(row0 + rl) * DIMD + ntile * 128;
#pragma unroll
                for (int nj = 0; nj < 4; ++nj) {
                    int col = n0 + nj * 8 + 2 * (lane & 3);
                    float2 v = make_float2(acc[mi][nj][h * 2], acc[mi][nj][h * 2 + 1]);
                    *(float2*)&g_OUTP[rowb + col] = v;
                }
            }
        }
}

// ---------------- combine ---------------------------------------------------
__global__ void combine_kernel(float* __restrict__ out, int out_size) {
    const int t = blockIdx.x, tid = threadIdx.x;
    float4 acc = make_float4(0.f, 0.f, 0.f, 0.f);
#pragma unroll
    for (int k = 0; k < TOPK; ++k) {
        int e = g_tok_e[t * TOPK + k];
        int row = g_offs[e] + g_tok_pos[t * TOPK + k];
        float w = g_tok_w[t * TOPK + k];
        float4 v = ((const float4*)(g_OUTP + (size_t)row * DIMD))[tid];
        acc.x += w * v.x; acc.y += w * v.y; acc.z += w * v.z; acc.w += w * v.w;
    }
    ((float4*)(out + (size_t)t * DIMD))[tid] = acc;
    if (t == 0 && tid == 0 && out_size > NTOK * DIMD)
        out[NTOK * DIMD] = 0.01f * g_aux / (float)(NTOK * NEXP);
}

// ---------------- launch -----------------------------------------------------
extern "C" void kernel_launch(void* const* d_in, const int* in_sizes, int n_in,
                              void* d_out, int out_size) {
    const float *x = 0, *rw = 0, *rb = 0, *w12 = 0, *w3 = 0;
    for (int i = 0; i < n_in; ++i) {
        switch (in_sizes[i]) {
            case 4194304:  x   = (const float*)d_in[i]; break;
            case 8192:     rw  = (const float*)d_in[i]; break;
            case 8:        rb  = (const float*)d_in[i]; break;
            case 67108864: w12 = (const float*)d_in[i]; break;
            case 33554432: w3  = (const float*)d_in[i]; break;
        }
    }
    if (!x || !rw || !rb || !w12 || !w3) {
        x = (const float*)d_in[0]; rw = (const float*)d_in[1]; rb = (const float*)d_in[2];
        w12 = (const float*)d_in[3]; w3 = (const float*)d_in[4];
    }
    float* out = (float*)d_out;

    cudaFuncSetAttribute(gemm1_kernel, cudaFuncAttributeMaxDynamicSharedMemorySize, G1_DYN);
    cudaFuncSetAttribute(gemm2_kernel, cudaFuncAttributeMaxDynamicSharedMemorySize, G2_DYN);

    prep_kernel<<<51201, 256>>>((const float4*)x, (const float4*)w12, (const float4*)w3);
    router_kernel<<<NTOK / 4, 128>>>(x, rw, rb);
    prefix_kernel<<<1, 1>>>();
    gemm1_kernel<<<dim3(64, 32, NEXP), 256, G1_DYN>>>();
    gemm2_kernel<<<dim3(32, 8, NEXP), 256, G2_DYN>>>();
    combine_kernel<<<NTOK, 256>>>(out, out_size);
}